// round 5
// baseline (speedup 1.0000x reference)
#include <cuda_runtime.h>
#include <cstdint>

#define NTHREADS 512

static constexpr int L  = 64;
static constexpr int D  = 128;
static constexpr int H  = 8;
static constexpr int DK = 16;

// Shared memory layout (floats):
//   xq   [64][128]  @ 0        (kept for residual)
//   xk   [64][128]  @ 8192     (reused as obuf in epilogue)
//   tvb  [64][128]  @ 16384
//   ctb  [64][128]  @ 24576
//   scratch         @ 32768  (14592 floats):
//     sh  [64][68], wqh/wkh/wvh [128][16], qh/kh/vh [64][16], xth [64][16]
static constexpr int SMEM_FLOATS = 32768 + 64*68 + 3*2048 + 4*1024;  // 47360
static constexpr int SMEM_BYTES  = SMEM_FLOATS * 4;                  // 189440

__global__ void __launch_bounds__(NTHREADS, 1)
fused_attn_kernel(const float* __restrict__ xq_g,
                  const float* __restrict__ xk_g,
                  const float* __restrict__ xt_g,
                  const float* __restrict__ Wq,  const float* __restrict__ bq,
                  const float* __restrict__ Wk,  const float* __restrict__ bk,
                  const float* __restrict__ Wv,  const float* __restrict__ bv,
                  const float* __restrict__ Wot, const float* __restrict__ bot,
                  const float* __restrict__ Wtg, const float* __restrict__ btg,
                  const float* __restrict__ g_time, const float* __restrict__ b_time,
                  const float* __restrict__ g_tgt,  const float* __restrict__ b_tgt,
                  float* __restrict__ out, int BN)
{
    extern __shared__ float sm[];
    float* xq  = sm;            // [64][128]
    float* xk  = sm + 8192;     // [64][128] -> obuf in epilogue
    float* tvb = sm + 16384;    // [64][128]
    float* ctb = sm + 24576;    // [64][128]
    float* scratch = sm + 32768;
    float* sh  = scratch;          // [64][68]
    float* wqh = scratch + 4352;   // [128][16]
    float* wkh = wqh + 2048;
    float* wvh = wkh + 2048;
    float* qh  = wvh + 2048;       // [64][16]
    float* kh  = qh + 1024;
    float* vh  = kh + 1024;
    float* xth = vh + 1024;        // [64][16]

    const int bn  = blockIdx.x;
    const int tid = threadIdx.x;

    const float* xq_src = xq_g + (size_t)bn * (L*D);
    const float* xk_src = xk_g + (size_t)bn * (L*D);
    const float* xt_src = xt_g + (size_t)bn * (L*D);

    const size_t attnElems = (size_t)BN * H * (L*L);
    float* tv_base = out + attnElems + (size_t)bn * (L*D);
    float* ct_base = out + attnElems + (size_t)BN * (L*D) + (size_t)bn * (L*D);

    // Load x_q, x_k tiles
    for (int i = tid; i < (L*D)/4; i += NTHREADS) {
        reinterpret_cast<float4*>(xq)[i] = reinterpret_cast<const float4*>(xq_src)[i];
        reinterpret_cast<float4*>(xk)[i] = reinterpret_cast<const float4*>(xk_src)[i];
    }
    __syncthreads();

    // ---------------- per-head stage ----------------
    for (int h = 0; h < H; ++h) {
        // stage W slices [128][16] for q,k,v and target slice [64][16]
        for (int i = tid; i < 512; i += NTHREADS) {   // 2048 floats -> 512 float4
            int d = i >> 2, c4 = i & 3;
            reinterpret_cast<float4*>(wqh)[i] =
                *(reinterpret_cast<const float4*>(Wq + d*D + h*DK) + c4);
            reinterpret_cast<float4*>(wkh)[i] =
                *(reinterpret_cast<const float4*>(Wk + d*D + h*DK) + c4);
            reinterpret_cast<float4*>(wvh)[i] =
                *(reinterpret_cast<const float4*>(Wv + d*D + h*DK) + c4);
        }
        for (int i = tid; i < 256; i += NTHREADS) {   // 1024 floats -> 256 float4
            int r = i >> 2, c4 = i & 3;
            reinterpret_cast<float4*>(xth)[i] =
                *(reinterpret_cast<const float4*>(xt_src + r*D + h*DK) + c4);
        }
        __syncthreads();

        // q_h, k_h, v_h : [64][16] = x @ Wslice + bias
        {
            const int c  = tid & 15;
            const int rb = tid >> 4;      // 0..31
            const int r0 = rb*2, r1 = r0 + 1;
            float aq0=0.f, aq1=0.f, ak0=0.f, ak1=0.f, av0=0.f, av1=0.f;
            for (int d0 = 0; d0 < D; d0 += 4) {
                float4 xa0 = *reinterpret_cast<const float4*>(xq + r0*D + d0);
                float4 xa1 = *reinterpret_cast<const float4*>(xq + r1*D + d0);
                float4 xb0 = *reinterpret_cast<const float4*>(xk + r0*D + d0);
                float4 xb1 = *reinterpret_cast<const float4*>(xk + r1*D + d0);
                float a0v[4], a1v[4], b0v[4], b1v[4];
                a0v[0]=xa0.x; a0v[1]=xa0.y; a0v[2]=xa0.z; a0v[3]=xa0.w;
                a1v[0]=xa1.x; a1v[1]=xa1.y; a1v[2]=xa1.z; a1v[3]=xa1.w;
                b0v[0]=xb0.x; b0v[1]=xb0.y; b0v[2]=xb0.z; b0v[3]=xb0.w;
                b1v[0]=xb1.x; b1v[1]=xb1.y; b1v[2]=xb1.z; b1v[3]=xb1.w;
                #pragma unroll
                for (int dd = 0; dd < 4; ++dd) {
                    float wq_ = wqh[(d0+dd)*DK + c];
                    float wk_ = wkh[(d0+dd)*DK + c];
                    float wv_ = wvh[(d0+dd)*DK + c];
                    aq0 += a0v[dd]*wq_;  aq1 += a1v[dd]*wq_;
                    ak0 += b0v[dd]*wk_;  ak1 += b1v[dd]*wk_;
                    av0 += b0v[dd]*wv_;  av1 += b1v[dd]*wv_;
                }
            }
            float bq_ = bq[h*DK + c], bk_ = bk[h*DK + c], bv_ = bv[h*DK + c];
            qh[r0*DK + c] = aq0 + bq_;  qh[r1*DK + c] = aq1 + bq_;
            kh[r0*DK + c] = ak0 + bk_;  kh[r1*DK + c] = ak1 + bk_;
            vh[r0*DK + c] = av0 + bv_;  vh[r1*DK + c] = av1 + bv_;
        }
        __syncthreads();

        // S_h [64][64] = q_h @ k_h^T * 0.25 ; write to smem + global attn output
        {
            const int kc = tid & 63;
            const int rg = tid >> 6;     // 0..7
            float kk[16];
            #pragma unroll
            for (int j = 0; j < 4; ++j) {
                float4 kv = *reinterpret_cast<const float4*>(kh + kc*DK + j*4);
                kk[4*j+0]=kv.x; kk[4*j+1]=kv.y; kk[4*j+2]=kv.z; kk[4*j+3]=kv.w;
            }
            float* attn_base = out + ((size_t)bn*H + h) * (L*L);
            #pragma unroll
            for (int i = 0; i < 8; ++i) {
                int r = rg*8 + i;
                float acc = 0.f;
                #pragma unroll
                for (int j = 0; j < 4; ++j) {
                    float4 qv = *reinterpret_cast<const float4*>(qh + r*DK + j*4);
                    acc += qv.x*kk[4*j] + qv.y*kk[4*j+1] + qv.z*kk[4*j+2] + qv.w*kk[4*j+3];
                }
                acc *= 0.25f;
                sh[r*68 + kc] = acc;
                attn_base[r*L + kc] = acc;
            }
        }
        __syncthreads();

        // tv_h = S_h @ v_h ; ct_h = S_h @ xt_h  -> accumulate head columns
        {
            const int c  = tid & 15;
            const int rb = tid >> 4;
            const int r0 = rb*2, r1 = r0 + 1;
            float atv0=0.f, atv1=0.f, act0=0.f, act1=0.f;
            for (int k0 = 0; k0 < L; k0 += 4) {
                float4 s0 = *reinterpret_cast<const float4*>(sh + r0*68 + k0);
                float4 s1 = *reinterpret_cast<const float4*>(sh + r1*68 + k0);
                float s0v[4], s1v[4];
                s0v[0]=s0.x; s0v[1]=s0.y; s0v[2]=s0.z; s0v[3]=s0.w;
                s1v[0]=s1.x; s1v[1]=s1.y; s1v[2]=s1.z; s1v[3]=s1.w;
                #pragma unroll
                for (int q = 0; q < 4; ++q) {
                    float vv = vh[(k0+q)*DK + c];
                    float tt = xth[(k0+q)*DK + c];
                    atv0 += s0v[q]*vv;  atv1 += s1v[q]*vv;
                    act0 += s0v[q]*tt;  act1 += s1v[q]*tt;
                }
            }
            tvb[r0*D + h*DK + c] = atv0;  tvb[r1*D + h*DK + c] = atv1;
            ctb[r0*D + h*DK + c] = act0;  ctb[r1*D + h*DK + c] = act1;
        }
        __syncthreads();
    }

    // ---------------- epilogue: output projections + LayerNorm ----------------
    float* obuf = xk;   // xk no longer needed
    for (int br = 0; br < 2; ++br) {
        const float* src  = br ? ctb : tvb;
        const float* W    = br ? Wtg : Wot;
        const float* bias = br ? btg : bot;

        for (int half = 0; half < 2; ++half) {
            __syncthreads();   // prior scratch/obuf consumers done
            // stage W[:, half*64 : half*64+64] -> ws [128][64]
            float* ws = scratch;
            for (int i = tid; i < (128*64)/4; i += NTHREADS) {  // 2048 float4
                int d = i >> 4, c4 = i & 15;
                reinterpret_cast<float4*>(ws)[i] =
                    *(reinterpret_cast<const float4*>(W + d*D + half*64) + c4);
            }
            __syncthreads();

            const int c0 = (tid & 15) * 4;
            const int rb = tid >> 4;
            const int r0 = rb*2, r1 = r0 + 1;
            float acc0[4], acc1[4];
            #pragma unroll
            for (int j = 0; j < 4; ++j) {
                acc0[j] = bias[half*64 + c0 + j];
                acc1[j] = acc0[j];
            }
            for (int d0 = 0; d0 < D; d0 += 4) {
                float4 a0 = *reinterpret_cast<const float4*>(src + r0*D + d0);
                float4 a1 = *reinterpret_cast<const float4*>(src + r1*D + d0);
                float a0v[4], a1v[4];
                a0v[0]=a0.x; a0v[1]=a0.y; a0v[2]=a0.z; a0v[3]=a0.w;
                a1v[0]=a1.x; a1v[1]=a1.y; a1v[2]=a1.z; a1v[3]=a1.w;
                #pragma unroll
                for (int dd = 0; dd < 4; ++dd) {
                    float4 w4 = *reinterpret_cast<const float4*>(ws + (d0+dd)*64 + c0);
                    acc0[0] += a0v[dd]*w4.x;  acc0[1] += a0v[dd]*w4.y;
                    acc0[2] += a0v[dd]*w4.z;  acc0[3] += a0v[dd]*w4.w;
                    acc1[0] += a1v[dd]*w4.x;  acc1[1] += a1v[dd]*w4.y;
                    acc1[2] += a1v[dd]*w4.z;  acc1[3] += a1v[dd]*w4.w;
                }
            }
            if (br == 0) {  // residual (time branch only)
                #pragma unroll
                for (int j = 0; j < 4; ++j) {
                    acc0[j] += xq[r0*D + half*64 + c0 + j];
                    acc1[j] += xq[r1*D + half*64 + c0 + j];
                }
            }
            *reinterpret_cast<float4*>(obuf + r0*D + half*64 + c0) =
                make_float4(acc0[0], acc0[1], acc0[2], acc0[3]);
            *reinterpret_cast<float4*>(obuf + r1*D + half*64 + c0) =
                make_float4(acc1[0], acc1[1], acc1[2], acc1[3]);
        }
        __syncthreads();

        // LayerNorm per row (population variance, eps 1e-5)
        {
            const float* g = br ? g_tgt : g_time;
            const float* b = br ? b_tgt : b_time;
            float* dst = br ? ct_base : tv_base;
            const int warp = tid >> 5, lane = tid & 31;
            #pragma unroll
            for (int i = 0; i < 4; ++i) {
                int r = warp*4 + i;
                float4 x = *reinterpret_cast<const float4*>(obuf + r*D + lane*4);
                float s1 = x.x + x.y + x.z + x.w;
                float s2 = x.x*x.x + x.y*x.y + x.z*x.z + x.w*x.w;
                #pragma unroll
                for (int o = 16; o; o >>= 1) {
                    s1 += __shfl_xor_sync(0xffffffffu, s1, o);
                    s2 += __shfl_xor_sync(0xffffffffu, s2, o);
                }
                float mean = s1 * (1.0f/128.0f);
                float var  = s2 * (1.0f/128.0f) - mean*mean;
                float rstd = rsqrtf(var + 1e-5f);
                float4 gv = *reinterpret_cast<const float4*>(g + lane*4);
                float4 bv2 = *reinterpret_cast<const float4*>(b + lane*4);
                float4 y;
                y.x = (x.x - mean)*rstd*gv.x + bv2.x;
                y.y = (x.y - mean)*rstd*gv.y + bv2.y;
                y.z = (x.z - mean)*rstd*gv.z + bv2.z;
                y.w = (x.w - mean)*rstd*gv.w + bv2.w;
                *reinterpret_cast<float4*>(dst + r*D + lane*4) = y;
            }
        }
        __syncthreads();  // obuf reused by next branch
    }
}

extern "C" void kernel_launch(void* const* d_in, const int* in_sizes, int n_in,
                              void* d_out, int out_size) {
    const float* xq   = (const float*)d_in[0];
    const float* xk   = (const float*)d_in[1];
    const float* xt   = (const float*)d_in[2];
    const float* Wq   = (const float*)d_in[3];
    const float* bq   = (const float*)d_in[4];
    const float* Wk   = (const float*)d_in[5];
    const float* bk   = (const float*)d_in[6];
    const float* Wv   = (const float*)d_in[7];
    const float* bv   = (const float*)d_in[8];
    const float* Wot  = (const float*)d_in[9];
    const float* bot  = (const float*)d_in[10];
    const float* Wtg  = (const float*)d_in[11];
    const float* btg  = (const float*)d_in[12];
    const float* g_time = (const float*)d_in[13];
    const float* b_time = (const float*)d_in[14];
    const float* g_tgt  = (const float*)d_in[15];
    const float* b_tgt  = (const float*)d_in[16];
    float* out = (float*)d_out;

    int BN = in_sizes[0] / (L * D);   // 828

    cudaFuncSetAttribute(fused_attn_kernel,
                         cudaFuncAttributeMaxDynamicSharedMemorySize, SMEM_BYTES);
    fused_attn_kernel<<<BN, NTHREADS, SMEM_BYTES>>>(
        xq, xk, xt, Wq, bq, Wk, bk, Wv, bv, Wot, bot, Wtg, btg,
        g_time, b_time, g_tgt, b_tgt, out, BN);
}

// round 7
// speedup vs baseline: 1.6698x; 1.6698x over previous
#include <cuda_runtime.h>

#define NT 512
typedef unsigned long long u64;

static constexpr int L = 64, D = 128, H = 8, DK = 16;

// smem float offsets
static constexpr int O_XQ  = 0;      // [64][128] xq (residual + A of Q-GEMM)
static constexpr int O_Q   = 8192;   // [64][128] Q -> TVB after phase C
static constexpr int O_V   = 16384;  // [64][128] V
static constexpr int O_KT  = 24576;  // [128][68] K transposed
static constexpr int O_XK  = 33280;  // [64][128] xk (phase A) -> CTB (phase C+)
static constexpr int O_W   = 41472;  // [128][128] W stage (phase A + epilogue)
static constexpr int O_S0  = 41472;  // [64][68] S head 0 of pair
static constexpr int O_S1  = 45824;  // [64][68] S head 1 of pair
static constexpr int O_XTS = 50176;  // [64][32] staged target cols of pair
static constexpr int SM_FLOATS = 57856;
static constexpr int SM_BYTES  = SM_FLOATS * 4;   // 231424 <= 232448

static __device__ __forceinline__ u64 pk2(float lo, float hi) {
    u64 r; asm("mov.b64 %0,{%1,%2};" : "=l"(r) : "f"(lo), "f"(hi)); return r;
}
static __device__ __forceinline__ u64 dup2(float v) {
    u64 r; asm("mov.b64 %0,{%1,%1};" : "=l"(r) : "f"(v)); return r;
}
static __device__ __forceinline__ void fma2(u64& d, u64 a, u64 b) {
    asm("fma.rn.f32x2 %0, %1, %2, %0;" : "+l"(d) : "l"(a), "l"(b));
}
static __device__ __forceinline__ float2 upk(u64 v) {
    float lo, hi; asm("mov.b64 {%0,%1}, %2;" : "=f"(lo), "=f"(hi) : "l"(v));
    return make_float2(lo, hi);
}

// 4x4 tile of a 64x128x128 GEMM. A row-major stride 128 (smem), ws [128][128] smem.
static __device__ __forceinline__ void gemm128(const float* __restrict__ A,
                                               const float* __restrict__ ws,
                                               u64 b0i, u64 b1i, int r0, int c0,
                                               float vals[4][4])
{
    u64 acc[4][2];
#pragma unroll
    for (int i = 0; i < 4; i++) { acc[i][0] = b0i; acc[i][1] = b1i; }
#pragma unroll 4
    for (int kk = 0; kk < 32; ++kk) {
        float av[4][4];
#pragma unroll
        for (int i = 0; i < 4; i++) {
            float4 a = *reinterpret_cast<const float4*>(A + (r0 + i) * D + 4 * kk);
            av[i][0] = a.x; av[i][1] = a.y; av[i][2] = a.z; av[i][3] = a.w;
        }
#pragma unroll
        for (int j = 0; j < 4; j++) {
            float4 b = *reinterpret_cast<const float4*>(ws + (4 * kk + j) * D + c0);
            u64 b0 = pk2(b.x, b.y), b1 = pk2(b.z, b.w);
#pragma unroll
            for (int i = 0; i < 4; i++) {
                u64 ad = dup2(av[i][j]);
                fma2(acc[i][0], ad, b0);
                fma2(acc[i][1], ad, b1);
            }
        }
    }
#pragma unroll
    for (int i = 0; i < 4; i++) {
        float2 p0 = upk(acc[i][0]), p1 = upk(acc[i][1]);
        vals[i][0] = p0.x; vals[i][1] = p0.y; vals[i][2] = p1.x; vals[i][3] = p1.y;
    }
}

__global__ void __launch_bounds__(NT, 1)
fused_attn_kernel(const float* __restrict__ xq_g, const float* __restrict__ xk_g,
                  const float* __restrict__ xt_g,
                  const float* __restrict__ Wq,  const float* __restrict__ bq,
                  const float* __restrict__ Wk,  const float* __restrict__ bk,
                  const float* __restrict__ Wv,  const float* __restrict__ bv,
                  const float* __restrict__ Wot, const float* __restrict__ bot,
                  const float* __restrict__ Wtg, const float* __restrict__ btg,
                  const float* __restrict__ g_time, const float* __restrict__ b_time,
                  const float* __restrict__ g_tgt,  const float* __restrict__ b_tgt,
                  float* __restrict__ out, int BN)
{
    extern __shared__ float sm[];
    const int bn = blockIdx.x, tid = threadIdx.x;

    const float* xq_src = xq_g + (size_t)bn * (L * D);
    const float* xk_src = xk_g + (size_t)bn * (L * D);
    const float* xt_src = xt_g + (size_t)bn * (L * D);

    const size_t attnElems = (size_t)BN * H * (L * L);
    float* tv_base = out + attnElems + (size_t)bn * (L * D);
    float* ct_base = out + attnElems + (size_t)BN * (L * D) + (size_t)bn * (L * D);

    const int rg = tid >> 5, cg = tid & 31;
    const int r0 = 4 * rg, c0 = 4 * cg;
    float* wst = sm + O_W;

    // ---- load xq, xk; stage Wq ----
    for (int i = tid; i < 2048; i += NT) {
        reinterpret_cast<float4*>(sm + O_XQ)[i] = __ldg(reinterpret_cast<const float4*>(xq_src) + i);
        reinterpret_cast<float4*>(sm + O_XK)[i] = __ldg(reinterpret_cast<const float4*>(xk_src) + i);
    }
    for (int i = tid; i < 4096; i += NT)
        reinterpret_cast<float4*>(wst)[i] = __ldg(reinterpret_cast<const float4*>(Wq) + i);
    __syncthreads();

    // ---- Q = xq @ Wq + bq ----
    {
        float4 bb = __ldg(reinterpret_cast<const float4*>(bq + c0));
        float vals[4][4];
        gemm128(sm + O_XQ, wst, pk2(bb.x, bb.y), pk2(bb.z, bb.w), r0, c0, vals);
#pragma unroll
        for (int i = 0; i < 4; i++)
            *reinterpret_cast<float4*>(sm + O_Q + (r0 + i) * D + c0) =
                make_float4(vals[i][0], vals[i][1], vals[i][2], vals[i][3]);
    }
    __syncthreads();
    for (int i = tid; i < 4096; i += NT)
        reinterpret_cast<float4*>(wst)[i] = __ldg(reinterpret_cast<const float4*>(Wk) + i);
    __syncthreads();

    // ---- K = xk @ Wk + bk, stored transposed: KT[c][r] ----
    {
        float4 bb = __ldg(reinterpret_cast<const float4*>(bk + c0));
        float vals[4][4];
        gemm128(sm + O_XK, wst, pk2(bb.x, bb.y), pk2(bb.z, bb.w), r0, c0, vals);
#pragma unroll
        for (int j = 0; j < 4; j++)
            *reinterpret_cast<float4*>(sm + O_KT + (c0 + j) * 68 + r0) =
                make_float4(vals[0][j], vals[1][j], vals[2][j], vals[3][j]);
    }
    __syncthreads();
    for (int i = tid; i < 4096; i += NT)
        reinterpret_cast<float4*>(wst)[i] = __ldg(reinterpret_cast<const float4*>(Wv) + i);
    __syncthreads();

    // ---- V = xk @ Wv + bv ----
    {
        float4 bb = __ldg(reinterpret_cast<const float4*>(bv + c0));
        float vals[4][4];
        gemm128(sm + O_XK, wst, pk2(bb.x, bb.y), pk2(bb.z, bb.w), r0, c0, vals);
#pragma unroll
        for (int i = 0; i < 4; i++)
            *reinterpret_cast<float4*>(sm + O_V + (r0 + i) * D + c0) =
                make_float4(vals[i][0], vals[i][1], vals[i][2], vals[i][3]);
    }
    __syncthreads();

    // ================= per head-pair: scores then apply =================
#pragma unroll 1
    for (int p = 0; p < 4; ++p) {
        // stage target cols of this pair: xts[k][0..31] = xt[k][32p..32p+31]
        {
            int k = tid >> 3, c4 = tid & 7;
            reinterpret_cast<float4*>(sm + O_XTS)[tid] =
                __ldg(reinterpret_cast<const float4*>(xt_src + k * D + p * 32 + 4 * c4));
        }
        // ---- S_h = Q_h @ K_h^T * 0.25 (2 heads x 256 threads) ----
        {
            const int t = tid & 255, hsel = tid >> 8;
            const int h = 2 * p + hsel;
            const int brg = t >> 4, bcg = t & 15;
            u64 acc[4][2];
#pragma unroll
            for (int i = 0; i < 4; i++) acc[i][0] = acc[i][1] = 0ull;
#pragma unroll
            for (int kk = 0; kk < 4; ++kk) {
                float av[4][4];
#pragma unroll
                for (int i = 0; i < 4; i++) {
                    float4 a = *reinterpret_cast<const float4*>(
                        sm + O_Q + (4 * brg + i) * D + h * DK + 4 * kk);
                    av[i][0] = a.x; av[i][1] = a.y; av[i][2] = a.z; av[i][3] = a.w;
                }
#pragma unroll
                for (int j = 0; j < 4; j++) {
                    float4 b = *reinterpret_cast<const float4*>(
                        sm + O_KT + (h * DK + 4 * kk + j) * 68 + 4 * bcg);
                    u64 b0 = pk2(b.x, b.y), b1 = pk2(b.z, b.w);
#pragma unroll
                    for (int i = 0; i < 4; i++) {
                        u64 ad = dup2(av[i][j]);
                        fma2(acc[i][0], ad, b0);
                        fma2(acc[i][1], ad, b1);
                    }
                }
            }
            float* Sh = sm + (hsel ? O_S1 : O_S0);
            float* attn = out + ((size_t)bn * H + h) * (L * L);
#pragma unroll
            for (int i = 0; i < 4; i++) {
                float2 p0 = upk(acc[i][0]), p1 = upk(acc[i][1]);
                float4 v = make_float4(p0.x * 0.25f, p0.y * 0.25f, p1.x * 0.25f, p1.y * 0.25f);
                *reinterpret_cast<float4*>(Sh + (4 * brg + i) * 68 + 4 * bcg) = v;
                *reinterpret_cast<float4*>(attn + (4 * brg + i) * L + 4 * bcg) = v;
            }
        }
        __syncthreads();
        // ---- TV_h = S_h @ V_h (sel 0) ; CT_h = S_h @ XT_h (sel 1) ----
        {
            const int t = tid & 255, hsel = tid >> 8;
            const int h = 2 * p + hsel;
            const int sel = t >> 7, q = t & 127;
            const int crg = q >> 2, ccg = q & 3;
            const float* Sh = sm + (hsel ? O_S1 : O_S0);
            const float* B = sel ? (sm + O_XTS) : (sm + O_V);
            const int bstride = sel ? 32 : D;
            const int bcol = sel ? (hsel * DK + 4 * ccg) : (h * DK + 4 * ccg);
            u64 acc[2][2] = {{0ull, 0ull}, {0ull, 0ull}};
#pragma unroll 4
            for (int kk = 0; kk < 16; ++kk) {
                float4 s0 = *reinterpret_cast<const float4*>(Sh + (2 * crg + 0) * 68 + 4 * kk);
                float4 s1 = *reinterpret_cast<const float4*>(Sh + (2 * crg + 1) * 68 + 4 * kk);
                float s0v[4] = {s0.x, s0.y, s0.z, s0.w};
                float s1v[4] = {s1.x, s1.y, s1.z, s1.w};
#pragma unroll
                for (int j = 0; j < 4; j++) {
                    float4 b = *reinterpret_cast<const float4*>(B + (4 * kk + j) * bstride + bcol);
                    u64 b0 = pk2(b.x, b.y), b1 = pk2(b.z, b.w);
                    u64 a0 = dup2(s0v[j]), a1 = dup2(s1v[j]);
                    fma2(acc[0][0], a0, b0); fma2(acc[0][1], a0, b1);
                    fma2(acc[1][0], a1, b0); fma2(acc[1][1], a1, b1);
                }
            }
            float* dst = sel ? (sm + O_XK) : (sm + O_Q);   // CTB : TVB
#pragma unroll
            for (int i = 0; i < 2; i++) {
                float2 p0 = upk(acc[i][0]), p1 = upk(acc[i][1]);
                *reinterpret_cast<float4*>(dst + (2 * crg + i) * D + h * DK + 4 * ccg) =
                    make_float4(p0.x, p0.y, p1.x, p1.y);
            }
        }
        __syncthreads();
    }

    // ================= epilogue: projection + LayerNorm x2 =================
#pragma unroll 1
    for (int br = 0; br < 2; ++br) {
        const float* W    = br ? Wtg : Wot;
        const float* bias = br ? btg : bot;
        const float* gam  = br ? g_tgt : g_time;
        const float* bet  = br ? b_tgt : b_time;
        const float* A    = sm + (br ? O_XK : O_Q);
        float* dst        = br ? ct_base : tv_base;

        for (int i = tid; i < 4096; i += NT)
            reinterpret_cast<float4*>(wst)[i] = __ldg(reinterpret_cast<const float4*>(W) + i);
        __syncthreads();

        float4 bb = __ldg(reinterpret_cast<const float4*>(bias + c0));
        float vals[4][4];
        gemm128(A, wst, pk2(bb.x, bb.y), pk2(bb.z, bb.w), r0, c0, vals);
        if (br == 0) {
#pragma unroll
            for (int i = 0; i < 4; i++) {
                float4 x = *reinterpret_cast<const float4*>(sm + O_XQ + (r0 + i) * D + c0);
                vals[i][0] += x.x; vals[i][1] += x.y; vals[i][2] += x.z; vals[i][3] += x.w;
            }
        }
        float4 gv = __ldg(reinterpret_cast<const float4*>(gam + c0));
        float4 bv2 = __ldg(reinterpret_cast<const float4*>(bet + c0));
#pragma unroll
        for (int i = 0; i < 4; i++) {
            float s1 = vals[i][0] + vals[i][1] + vals[i][2] + vals[i][3];
            float s2 = vals[i][0]*vals[i][0] + vals[i][1]*vals[i][1]
                     + vals[i][2]*vals[i][2] + vals[i][3]*vals[i][3];
#pragma unroll
            for (int o = 16; o; o >>= 1) {
                s1 += __shfl_xor_sync(0xffffffffu, s1, o);
                s2 += __shfl_xor_sync(0xffffffffu, s2, o);
            }
            float mean = s1 * (1.0f / 128.0f);
            float var  = s2 * (1.0f / 128.0f) - mean * mean;
            float rstd = rsqrtf(var + 1e-5f);
            float4 y;
            y.x = (vals[i][0] - mean) * rstd * gv.x + bv2.x;
            y.y = (vals[i][1] - mean) * rstd * gv.y + bv2.y;
            y.z = (vals[i][2] - mean) * rstd * gv.z + bv2.z;
            y.w = (vals[i][3] - mean) * rstd * gv.w + bv2.w;
            *reinterpret_cast<float4*>(dst + (r0 + i) * D + c0) = y;
        }
        __syncthreads();
    }
}

extern "C" void kernel_launch(void* const* d_in, const int* in_sizes, int n_in,
                              void* d_out, int out_size) {
    const float* xq  = (const float*)d_in[0];
    const float* xk  = (const float*)d_in[1];
    const float* xt  = (const float*)d_in[2];
    const float* Wq  = (const float*)d_in[3];
    const float* bq  = (const float*)d_in[4];
    const float* Wk  = (const float*)d_in[5];
    const float* bk  = (const float*)d_in[6];
    const float* Wv  = (const float*)d_in[7];
    const float* bv  = (const float*)d_in[8];
    const float* Wot = (const float*)d_in[9];
    const float* bot = (const float*)d_in[10];
    const float* Wtg = (const float*)d_in[11];
    const float* btg = (const float*)d_in[12];
    const float* g_time = (const float*)d_in[13];
    const float* b_time = (const float*)d_in[14];
    const float* g_tgt  = (const float*)d_in[15];
    const float* b_tgt  = (const float*)d_in[16];
    float* out = (float*)d_out;

    int BN = in_sizes[0] / (L * D);

    cudaFuncSetAttribute(fused_attn_kernel,
                         cudaFuncAttributeMaxDynamicSharedMemorySize, SM_BYTES);
    fused_attn_kernel<<<BN, NT, SM_BYTES>>>(
        xq, xk, xt, Wq, bq, Wk, bk, Wv, bv, Wot, bot, Wtg, btg,
        g_time, b_time, g_tgt, b_tgt, out, BN);
}

// round 8
// speedup vs baseline: 1.7450x; 1.0451x over previous
#include <cuda_runtime.h>

#define NT 512
typedef unsigned long long u64;
typedef unsigned int u32;

static constexpr int L = 64, D = 128, H = 8, DK = 16;

// smem float offsets
static constexpr int O_XQ  = 0;      // [64][128] xq (residual + A of Q-GEMM)
static constexpr int O_XK  = 8192;   // [64][128] xk -> CTB after apply
static constexpr int O_Q   = 16384;  // [64][128] Q -> TVB after apply
static constexpr int O_V   = 24576;  // [64][128] V
static constexpr int O_KT  = 32768;  // [128][68] K transposed (rotated)
static constexpr int O_WB0 = 41472;  // [64][128] W chunk buf 0
static constexpr int O_WB1 = 49664;  // [64][128] W chunk buf 1
static constexpr int O_S0  = 41472;  // [64][68]  (overlaps WB, disjoint in time)
static constexpr int O_S1  = 45824;  // [64][68]
static constexpr int O_XTS = 50176;  // [64][32]
static constexpr int SM_FLOATS = 57856;
static constexpr int SM_BYTES  = SM_FLOATS * 4;  // 231424

static __device__ __forceinline__ u64 pk2(float lo, float hi) {
    u64 r; asm("mov.b64 %0,{%1,%2};" : "=l"(r) : "f"(lo), "f"(hi)); return r;
}
static __device__ __forceinline__ u64 dup2(float v) {
    u64 r; asm("mov.b64 %0,{%1,%1};" : "=l"(r) : "f"(v)); return r;
}
static __device__ __forceinline__ void fma2(u64& d, u64 a, u64 b) {
    asm("fma.rn.f32x2 %0, %1, %2, %0;" : "+l"(d) : "l"(a), "l"(b));
}
static __device__ __forceinline__ float2 upk(u64 v) {
    float lo, hi; asm("mov.b64 {%0,%1}, %2;" : "=f"(lo), "=f"(hi) : "l"(v));
    return make_float2(lo, hi);
}

static __device__ __forceinline__ void cpa16(float* dst, const float* src) {
    u32 d = (u32)__cvta_generic_to_shared(dst);
    asm volatile("cp.async.cg.shared.global [%0], [%1], 16;" :: "r"(d), "l"(src));
}
static __device__ __forceinline__ void cpa_commit() {
    asm volatile("cp.async.commit_group;");
}
template<int N> static __device__ __forceinline__ void cpa_wait() {
    asm volatile("cp.async.wait_group %0;" :: "n"(N));
}
// stage one 64-row x 128-col weight chunk (32KB) as one cp.async group
static __device__ __forceinline__ void stage_w(float* dst, const float* src, int tid) {
    for (int i = tid; i < 2048; i += NT) cpa16(dst + 4 * i, src + 4 * i);
    cpa_commit();
}

// half-GEMM, 8 rows x 2 packed cols per thread. A [64][128] smem, wb [64][128] chunk.
static __device__ __forceinline__ void hg82(const float* __restrict__ A,
                                            const float* __restrict__ wb,
                                            int r0, int c0, int kb, u64 acc[8])
{
#pragma unroll 2
    for (int kk = 0; kk < 16; ++kk) {
        float4 a[8];
#pragma unroll
        for (int i = 0; i < 8; i++)
            a[i] = *reinterpret_cast<const float4*>(A + (r0 + i) * D + kb + 4 * kk);
#pragma unroll
        for (int j = 0; j < 4; j++) {
            u64 b = *reinterpret_cast<const u64*>(wb + (4 * kk + j) * D + c0);
#pragma unroll
            for (int i = 0; i < 8; i++) {
                float av = (j == 0) ? a[i].x : (j == 1) ? a[i].y : (j == 2) ? a[i].z : a[i].w;
                fma2(acc[i], dup2(av), b);
            }
        }
    }
}

// half-GEMM, 4 rows x 4 cols per thread (epilogue; warp spans full row for LN).
static __device__ __forceinline__ void hg44(const float* __restrict__ A,
                                            const float* __restrict__ wb,
                                            int r0, int c0, int kb, u64 acc[4][2])
{
#pragma unroll 2
    for (int kk = 0; kk < 16; ++kk) {
        float4 a[4];
#pragma unroll
        for (int i = 0; i < 4; i++)
            a[i] = *reinterpret_cast<const float4*>(A + (r0 + i) * D + kb + 4 * kk);
#pragma unroll
        for (int j = 0; j < 4; j++) {
            float4 b = *reinterpret_cast<const float4*>(wb + (4 * kk + j) * D + c0);
            u64 b0 = pk2(b.x, b.y), b1 = pk2(b.z, b.w);
#pragma unroll
            for (int i = 0; i < 4; i++) {
                float av = (j == 0) ? a[i].x : (j == 1) ? a[i].y : (j == 2) ? a[i].z : a[i].w;
                u64 ad = dup2(av);
                fma2(acc[i][0], ad, b0);
                fma2(acc[i][1], ad, b1);
            }
        }
    }
}

__global__ void __launch_bounds__(NT, 1)
fused_attn_kernel(const float* __restrict__ xq_g, const float* __restrict__ xk_g,
                  const float* __restrict__ xt_g,
                  const float* __restrict__ Wq,  const float* __restrict__ bq,
                  const float* __restrict__ Wk,  const float* __restrict__ bk,
                  const float* __restrict__ Wv,  const float* __restrict__ bv,
                  const float* __restrict__ Wot, const float* __restrict__ bot,
                  const float* __restrict__ Wtg, const float* __restrict__ btg,
                  const float* __restrict__ g_time, const float* __restrict__ b_time,
                  const float* __restrict__ g_tgt,  const float* __restrict__ b_tgt,
                  float* __restrict__ out, int BN)
{
    extern __shared__ float sm[];
    const int bn = blockIdx.x, tid = threadIdx.x;

    const float* xq_src = xq_g + (size_t)bn * (L * D);
    const float* xk_src = xk_g + (size_t)bn * (L * D);
    const float* xt_src = xt_g + (size_t)bn * (L * D);

    const size_t attnElems = (size_t)BN * H * (L * L);
    float* tv_base = out + attnElems + (size_t)bn * (L * D);
    float* ct_base = out + attnElems + (size_t)BN * (L * D) + (size_t)bn * (L * D);

    // phase-A mapping: 8 rows x 2 cols
    const int r0a = 8 * (tid >> 6);
    const int c0a = 2 * (tid & 63);
    // epilogue mapping: 4 rows x 4 cols (warp = full row)
    const int r0e = 4 * (tid >> 5);
    const int c0e = 4 * (tid & 31);

    float* WB0 = sm + O_WB0;
    float* WB1 = sm + O_WB1;

    // ---- group0: xq, xk, Wq.h0 ; group1: Wq.h1 ----
    for (int i = tid; i < 2048; i += NT) {
        cpa16(sm + O_XQ + 4 * i, xq_src + 4 * i);
        cpa16(sm + O_XK + 4 * i, xk_src + 4 * i);
        cpa16(WB0 + 4 * i, Wq + 4 * i);
    }
    cpa_commit();
    stage_w(WB1, Wq + 8192, tid);

    u64 acc8[8];

    // ================= Q = xq @ Wq + bq =================
    cpa_wait<1>(); __syncthreads();
    {
        float2 bb = *reinterpret_cast<const float2*>(bq + c0a);
        u64 bi = pk2(bb.x, bb.y);
#pragma unroll
        for (int i = 0; i < 8; i++) acc8[i] = bi;
    }
    hg82(sm + O_XQ, WB0, r0a, c0a, 0, acc8);
    __syncthreads();
    stage_w(WB0, Wk, tid);
    cpa_wait<1>(); __syncthreads();
    hg82(sm + O_XQ, WB1, r0a, c0a, 64, acc8);
#pragma unroll
    for (int i = 0; i < 8; i++)
        *reinterpret_cast<float2*>(sm + O_Q + (r0a + i) * D + c0a) = upk(acc8[i]);
    __syncthreads();
    stage_w(WB1, Wk + 8192, tid);

    // ================= K = xk @ Wk + bk -> KT (rotated) =================
    cpa_wait<1>(); __syncthreads();
    {
        float2 bb = *reinterpret_cast<const float2*>(bk + c0a);
        u64 bi = pk2(bb.x, bb.y);
#pragma unroll
        for (int i = 0; i < 8; i++) acc8[i] = bi;
    }
    hg82(sm + O_XK, WB0, r0a, c0a, 0, acc8);
    __syncthreads();
    stage_w(WB0, Wv, tid);
    cpa_wait<1>(); __syncthreads();
    hg82(sm + O_XK, WB1, r0a, c0a, 64, acc8);
    {
        float va[2][8];
#pragma unroll
        for (int i = 0; i < 8; i++) {
            float2 p = upk(acc8[i]);
            va[0][i] = p.x; va[1][i] = p.y;
        }
#pragma unroll
        for (int cc = 0; cc < 2; ++cc) {
            int c = c0a + cc;
            int rot = (4 * (c >> 1)) & 63;
            *reinterpret_cast<float4*>(sm + O_KT + c * 68 + ((r0a + rot) & 63)) =
                make_float4(va[cc][0], va[cc][1], va[cc][2], va[cc][3]);
            *reinterpret_cast<float4*>(sm + O_KT + c * 68 + ((r0a + 4 + rot) & 63)) =
                make_float4(va[cc][4], va[cc][5], va[cc][6], va[cc][7]);
        }
    }
    __syncthreads();
    stage_w(WB1, Wv + 8192, tid);

    // ================= V = xk @ Wv + bv =================
    cpa_wait<1>(); __syncthreads();
    {
        float2 bb = *reinterpret_cast<const float2*>(bv + c0a);
        u64 bi = pk2(bb.x, bb.y);
#pragma unroll
        for (int i = 0; i < 8; i++) acc8[i] = bi;
    }
    hg82(sm + O_XK, WB0, r0a, c0a, 0, acc8);
    cpa_wait<0>(); __syncthreads();
    hg82(sm + O_XK, WB1, r0a, c0a, 64, acc8);
#pragma unroll
    for (int i = 0; i < 8; i++)
        *reinterpret_cast<float2*>(sm + O_V + (r0a + i) * D + c0a) = upk(acc8[i]);
    __syncthreads();

    // ================= per head-pair: scores then apply =================
#pragma unroll 1
    for (int p = 0; p < 4; ++p) {
        // stage target cols of this pair: xts[k][0..31] = xt[k][32p..32p+31]
        {
            int k = tid >> 3, c4 = tid & 7;
            reinterpret_cast<float4*>(sm + O_XTS)[tid] =
                __ldg(reinterpret_cast<const float4*>(xt_src + k * D + p * 32 + 4 * c4));
        }
        // ---- S_h = Q_h @ K_h^T * 0.25 (2 heads x 256 threads) ----
        {
            const int t = tid & 255, hsel = tid >> 8;
            const int h = 2 * p + hsel;
            const int brg = t >> 4, bcg = t & 15;
            u64 acc[4][2];
#pragma unroll
            for (int i = 0; i < 4; i++) acc[i][0] = acc[i][1] = 0ull;
#pragma unroll
            for (int kk = 0; kk < 4; ++kk) {
                float av[4][4];
#pragma unroll
                for (int i = 0; i < 4; i++) {
                    float4 a = *reinterpret_cast<const float4*>(
                        sm + O_Q + (4 * brg + i) * D + h * DK + 4 * kk);
                    av[i][0] = a.x; av[i][1] = a.y; av[i][2] = a.z; av[i][3] = a.w;
                }
#pragma unroll
                for (int j = 0; j < 4; j++) {
                    int c = h * DK + 4 * kk + j;
                    int rot = (4 * (c >> 1)) & 63;
                    float4 b = *reinterpret_cast<const float4*>(
                        sm + O_KT + c * 68 + ((4 * bcg + rot) & 63));
                    u64 b0 = pk2(b.x, b.y), b1 = pk2(b.z, b.w);
#pragma unroll
                    for (int i = 0; i < 4; i++) {
                        u64 ad = dup2(av[i][j]);
                        fma2(acc[i][0], ad, b0);
                        fma2(acc[i][1], ad, b1);
                    }
                }
            }
            float* Sh = sm + (hsel ? O_S1 : O_S0);
            float* attn = out + ((size_t)bn * H + h) * (L * L);
#pragma unroll
            for (int i = 0; i < 4; i++) {
                float2 p0 = upk(acc[i][0]), p1 = upk(acc[i][1]);
                float4 v = make_float4(p0.x * 0.25f, p0.y * 0.25f, p1.x * 0.25f, p1.y * 0.25f);
                *reinterpret_cast<float4*>(Sh + (4 * brg + i) * 68 + 4 * bcg) = v;
                *reinterpret_cast<float4*>(attn + (4 * brg + i) * L + 4 * bcg) = v;
            }
        }
        __syncthreads();
        // ---- TV_h = S_h @ V_h (sel 0) ; CT_h = S_h @ XT_h (sel 1) ----
        {
            const int t = tid & 255, hsel = tid >> 8;
            const int h = 2 * p + hsel;
            const int sel = t >> 7, q = t & 127;
            const int crg = q >> 2, ccg = q & 3;
            const float* Sh = sm + (hsel ? O_S1 : O_S0);
            const float* B = sel ? (sm + O_XTS) : (sm + O_V);
            const int bstride = sel ? 32 : D;
            const int bcol = sel ? (hsel * DK + 4 * ccg) : (h * DK + 4 * ccg);
            u64 acc[2][2] = {{0ull, 0ull}, {0ull, 0ull}};
#pragma unroll 4
            for (int kk = 0; kk < 16; ++kk) {
                float4 s0 = *reinterpret_cast<const float4*>(Sh + (2 * crg + 0) * 68 + 4 * kk);
                float4 s1 = *reinterpret_cast<const float4*>(Sh + (2 * crg + 1) * 68 + 4 * kk);
                float s0v[4] = {s0.x, s0.y, s0.z, s0.w};
                float s1v[4] = {s1.x, s1.y, s1.z, s1.w};
#pragma unroll
                for (int j = 0; j < 4; j++) {
                    float4 b = *reinterpret_cast<const float4*>(B + (4 * kk + j) * bstride + bcol);
                    u64 b0 = pk2(b.x, b.y), b1 = pk2(b.z, b.w);
                    u64 a0 = dup2(s0v[j]), a1 = dup2(s1v[j]);
                    fma2(acc[0][0], a0, b0); fma2(acc[0][1], a0, b1);
                    fma2(acc[1][0], a1, b0); fma2(acc[1][1], a1, b1);
                }
            }
            float* dst = sel ? (sm + O_XK) : (sm + O_Q);   // CTB : TVB
#pragma unroll
            for (int i = 0; i < 2; i++) {
                float2 p0 = upk(acc[i][0]), p1 = upk(acc[i][1]);
                *reinterpret_cast<float4*>(dst + (2 * crg + i) * D + h * DK + 4 * ccg) =
                    make_float4(p0.x, p0.y, p1.x, p1.y);
            }
        }
        __syncthreads();
    }

    // ================= epilogue: projection + LayerNorm x2 (pipelined W) =====
    stage_w(WB0, Wot, tid);
    stage_w(WB1, Wot + 8192, tid);

    u64 accE[4][2];
    float vals[4][4];
    float4 gv, bv2;

    // ---- time branch: TVB @ Wot + bot + residual, LN ----
    cpa_wait<1>(); __syncthreads();
    {
        float4 bb = __ldg(reinterpret_cast<const float4*>(bot + c0e));
        u64 b0 = pk2(bb.x, bb.y), b1 = pk2(bb.z, bb.w);
#pragma unroll
        for (int i = 0; i < 4; i++) { accE[i][0] = b0; accE[i][1] = b1; }
    }
    hg44(sm + O_Q, WB0, r0e, c0e, 0, accE);
    __syncthreads();
    stage_w(WB0, Wtg, tid);
    cpa_wait<1>(); __syncthreads();
    hg44(sm + O_Q, WB1, r0e, c0e, 64, accE);
#pragma unroll
    for (int i = 0; i < 4; i++) {
        float2 p0 = upk(accE[i][0]), p1 = upk(accE[i][1]);
        float4 x = *reinterpret_cast<const float4*>(sm + O_XQ + (r0e + i) * D + c0e);
        vals[i][0] = p0.x + x.x; vals[i][1] = p0.y + x.y;
        vals[i][2] = p1.x + x.z; vals[i][3] = p1.y + x.w;
    }
    gv  = __ldg(reinterpret_cast<const float4*>(g_time + c0e));
    bv2 = __ldg(reinterpret_cast<const float4*>(b_time + c0e));
#pragma unroll
    for (int i = 0; i < 4; i++) {
        float s1 = vals[i][0] + vals[i][1] + vals[i][2] + vals[i][3];
        float s2 = vals[i][0]*vals[i][0] + vals[i][1]*vals[i][1]
                 + vals[i][2]*vals[i][2] + vals[i][3]*vals[i][3];
#pragma unroll
        for (int o = 16; o; o >>= 1) {
            s1 += __shfl_xor_sync(0xffffffffu, s1, o);
            s2 += __shfl_xor_sync(0xffffffffu, s2, o);
        }
        float mean = s1 * (1.0f / 128.0f);
        float var  = s2 * (1.0f / 128.0f) - mean * mean;
        float rstd = rsqrtf(var + 1e-5f);
        float4 y;
        y.x = (vals[i][0] - mean) * rstd * gv.x + bv2.x;
        y.y = (vals[i][1] - mean) * rstd * gv.y + bv2.y;
        y.z = (vals[i][2] - mean) * rstd * gv.z + bv2.z;
        y.w = (vals[i][3] - mean) * rstd * gv.w + bv2.w;
        *reinterpret_cast<float4*>(tv_base + (r0e + i) * D + c0e) = y;
    }
    __syncthreads();
    stage_w(WB1, Wtg + 8192, tid);

    // ---- target branch: CTB @ Wtg + btg, LN ----
    cpa_wait<1>(); __syncthreads();
    {
        float4 bb = __ldg(reinterpret_cast<const float4*>(btg + c0e));
        u64 b0 = pk2(bb.x, bb.y), b1 = pk2(bb.z, bb.w);
#pragma unroll
        for (int i = 0; i < 4; i++) { accE[i][0] = b0; accE[i][1] = b1; }
    }
    hg44(sm + O_XK, WB0, r0e, c0e, 0, accE);
    cpa_wait<0>(); __syncthreads();
    hg44(sm + O_XK, WB1, r0e, c0e, 64, accE);
#pragma unroll
    for (int i = 0; i < 4; i++) {
        float2 p0 = upk(accE[i][0]), p1 = upk(accE[i][1]);
        vals[i][0] = p0.x; vals[i][1] = p0.y; vals[i][2] = p1.x; vals[i][3] = p1.y;
    }
    gv  = __ldg(reinterpret_cast<const float4*>(g_tgt + c0e));
    bv2 = __ldg(reinterpret_cast<const float4*>(b_tgt + c0e));
#pragma unroll
    for (int i = 0; i < 4; i++) {
        float s1 = vals[i][0] + vals[i][1] + vals[i][2] + vals[i][3];
        float s2 = vals[i][0]*vals[i][0] + vals[i][1]*vals[i][1]
                 + vals[i][2]*vals[i][2] + vals[i][3]*vals[i][3];
#pragma unroll
        for (int o = 16; o; o >>= 1) {
            s1 += __shfl_xor_sync(0xffffffffu, s1, o);
            s2 += __shfl_xor_sync(0xffffffffu, s2, o);
        }
        float mean = s1 * (1.0f / 128.0f);
        float var  = s2 * (1.0f / 128.0f) - mean * mean;
        float rstd = rsqrtf(var + 1e-5f);
        float4 y;
        y.x = (vals[i][0] - mean) * rstd * gv.x + bv2.x;
        y.y = (vals[i][1] - mean) * rstd * gv.y + bv2.y;
        y.z = (vals[i][2] - mean) * rstd * gv.z + bv2.z;
        y.w = (vals[i][3] - mean) * rstd * gv.w + bv2.w;
        *reinterpret_cast<float4*>(ct_base + (r0e + i) * D + c0e) = y;
    }
}

extern "C" void kernel_launch(void* const* d_in, const int* in_sizes, int n_in,
                              void* d_out, int out_size) {
    const float* xq  = (const float*)d_in[0];
    const float* xk  = (const float*)d_in[1];
    const float* xt  = (const float*)d_in[2];
    const float* Wq  = (const float*)d_in[3];
    const float* bq  = (const float*)d_in[4];
    const float* Wk  = (const float*)d_in[5];
    const float* bk  = (const float*)d_in[6];
    const float* Wv  = (const float*)d_in[7];
    const float* bv  = (const float*)d_in[8];
    const float* Wot = (const float*)d_in[9];
    const float* bot = (const float*)d_in[10];
    const float* Wtg = (const float*)d_in[11];
    const float* btg = (const float*)d_in[12];
    const float* g_time = (const float*)d_in[13];
    const float* b_time = (const float*)d_in[14];
    const float* g_tgt  = (const float*)d_in[15];
    const float* b_tgt  = (const float*)d_in[16];
    float* out = (float*)d_out;

    int BN = in_sizes[0] / (L * D);

    cudaFuncSetAttribute(fused_attn_kernel,
                         cudaFuncAttributeMaxDynamicSharedMemorySize, SM_BYTES);
    fused_attn_kernel<<<BN, NT, SM_BYTES>>>(
        xq, xk, xt, Wq, bq, Wk, bk, Wv, bv, Wot, bot, Wtg, btg,
        g_time, b_time, g_tgt, b_tgt, out, BN);
}